// round 2
// baseline (speedup 1.0000x reference)
#include <cuda_runtime.h>
#include <cstdint>

#define B_SZ 16384
#define F_SZ 9000
#define ACC_N 128

// Scratch: [B][256] fp32. white accum -> cols [0,128), black accum -> cols [128,256).
__device__ float g_scratch[B_SZ * 256];
__device__ unsigned char g_stm[B_SZ];

__device__ __forceinline__ float screlu(float x) {
    x = fminf(fmaxf(x, 0.0f), 1.0f);
    return x * x;
}

// ---------------------------------------------------------------------------
// Kernel 0: detect stm dtype (uint8 bool / int32 / float32) and canonicalize
// into g_stm as 0/1 bytes. Single block; reads only the first 16384 bytes for
// detection (safe for all candidate dtypes), then converts with the detected
// stride.
// ---------------------------------------------------------------------------
__global__ void stm_convert_kernel(const unsigned char* __restrict__ p) {
    __shared__ int fFloat, fBool;
    if (threadIdx.x == 0) { fFloat = 0; fBool = 0; }
    __syncthreads();
    int lf = 0, lb = 0;
    for (int i = threadIdx.x; i < B_SZ; i += blockDim.x) {
        unsigned char v = p[i];
        if (v == 0x80u || v == 0x3fu) lf = 1;          // bytes of 1.0f
        else if (v != 0u && (i & 3) != 0) lb = 1;      // nonzero off 4-alignment
    }
    if (lf) atomicOr(&fFloat, 1);
    if (lb) atomicOr(&fBool, 1);
    __syncthreads();
    const int mode = fFloat ? 2 : (fBool ? 1 : 0);
    for (int i = threadIdx.x; i < B_SZ; i += blockDim.x) {
        unsigned char s;
        if (mode == 2)      s = (((const float*)(const void*)p)[i] != 0.0f);
        else if (mode == 1) s = (p[i] != 0u);
        else                s = (((const int*)(const void*)p)[i] != 0);
        g_stm[i] = s;
    }
}

// ---------------------------------------------------------------------------
// Kernel 1: fused feature-transform GEMM + bias + screlu.
//   C[b, n] = screlu( features[b, :] . ft_w[n, :] + ft_b[n] )
// gridDim = (B/128, 2), blockIdx.y = color (0 = white, 1 = black).
// 256 threads, 128x128 tile, TK=8, 8x8 register micro-tile.
// ---------------------------------------------------------------------------
__global__ __launch_bounds__(256, 2)
void ft_kernel(const float* __restrict__ white,
               const float* __restrict__ black,
               const float* __restrict__ ftw,
               const float* __restrict__ ftb) {
    constexpr int TM = 128, TK = 8;

    __shared__ float As[TK][TM];   // [k][m]
    __shared__ float Bs[TK][TM];   // [k][n]

    const int t = threadIdx.x;
    const int color = blockIdx.y;
    const float* __restrict__ A = color ? black : white;
    const int row0 = blockIdx.x * TM;

    // Load mapping: each thread fetches one float4 of A and one of B per tile.
    const int lm = t >> 1;            // row (A) / accum index (B): 0..127
    const int lk = (t & 1) << 2;      // 0 or 4
    const float* aPtr = A   + (size_t)(row0 + lm) * F_SZ + lk;
    const float* bPtr = ftw + (size_t)lm * F_SZ + lk;

    // First tile
    float4 a4 = *(const float4*)aPtr;
    float4 b4 = *(const float4*)bPtr;
    As[lk + 0][lm] = a4.x; As[lk + 1][lm] = a4.y;
    As[lk + 2][lm] = a4.z; As[lk + 3][lm] = a4.w;
    Bs[lk + 0][lm] = b4.x; Bs[lk + 1][lm] = b4.y;
    Bs[lk + 2][lm] = b4.z; Bs[lk + 3][lm] = b4.w;
    __syncthreads();

    const int tx = t & 15;     // col group: cols tx*8 .. tx*8+7
    const int ty = t >> 4;     // row group: rows ty*8 .. ty*8+7

    float acc[8][8];
#pragma unroll
    for (int i = 0; i < 8; i++)
#pragma unroll
        for (int j = 0; j < 8; j++) acc[i][j] = 0.0f;

    for (int k0 = TK;; k0 += TK) {
        const bool more = (k0 < F_SZ);
        float4 an, bn;
        if (more) {
            an = *(const float4*)(aPtr + k0);
            bn = *(const float4*)(bPtr + k0);
        }

#pragma unroll
        for (int kk = 0; kk < TK; kk++) {
            float a[8], b[8];
            *(float4*)(a)     = *(const float4*)&As[kk][ty * 8];
            *(float4*)(a + 4) = *(const float4*)&As[kk][ty * 8 + 4];
            *(float4*)(b)     = *(const float4*)&Bs[kk][tx * 8];
            *(float4*)(b + 4) = *(const float4*)&Bs[kk][tx * 8 + 4];
#pragma unroll
            for (int i = 0; i < 8; i++)
#pragma unroll
                for (int j = 0; j < 8; j++)
                    acc[i][j] += a[i] * b[j];
        }
        __syncthreads();
        if (!more) break;
        As[lk + 0][lm] = an.x; As[lk + 1][lm] = an.y;
        As[lk + 2][lm] = an.z; As[lk + 3][lm] = an.w;
        Bs[lk + 0][lm] = bn.x; Bs[lk + 1][lm] = bn.y;
        Bs[lk + 2][lm] = bn.z; Bs[lk + 3][lm] = bn.w;
        __syncthreads();
    }

    // Epilogue: + ft_b, screlu, write to scratch (color selects column half).
    const float4 bb0 = *(const float4*)(ftb + tx * 8);
    const float4 bb1 = *(const float4*)(ftb + tx * 8 + 4);
    const float bias[8] = {bb0.x, bb0.y, bb0.z, bb0.w, bb1.x, bb1.y, bb1.z, bb1.w};

#pragma unroll
    for (int i = 0; i < 8; i++) {
        const int r = row0 + ty * 8 + i;
        float v[8];
#pragma unroll
        for (int j = 0; j < 8; j++) v[j] = screlu(acc[i][j] + bias[j]);
        float* dst = g_scratch + (size_t)r * 256 + color * ACC_N + tx * 8;
        *(float4*)(dst)     = make_float4(v[0], v[1], v[2], v[3]);
        *(float4*)(dst + 4) = make_float4(v[4], v[5], v[6], v[7]);
    }
}

// ---------------------------------------------------------------------------
// Kernel 2: tail MLP. One warp per batch row.
//   x = [stm_accum, nstm_accum]  (index rotation of scratch by 128 if stm)
//   x1 = screlu(l1_w @ x + l1_b)          (32)
//   x2 = screlu(l2_w @ x1 + l2_b)         (32)
//   out = out_w @ x2 + out_b              (1)
// ---------------------------------------------------------------------------
__global__ __launch_bounds__(256)
void tail_kernel(const float* __restrict__ l1w, const float* __restrict__ l1b,
                 const float* __restrict__ l2w, const float* __restrict__ l2b,
                 const float* __restrict__ outw, const float* __restrict__ outb,
                 float* __restrict__ out) {
    __shared__ float l1wT[256 * 32];   // [k][i] transposed -> conflict-free
    __shared__ float l1b_s[32];
    __shared__ float l2wT[32 * 32];    // [j][i]
    __shared__ float l2b_s[32];
    __shared__ float outw_s[32];
    __shared__ float xs[8][256];
    __shared__ float x1s[8][32];

    const int t = threadIdx.x;
    // Stage weights (transposed)
    for (int idx = t; idx < 32 * 256; idx += 256) {
        int i = idx >> 8, k = idx & 255;
        l1wT[k * 32 + i] = l1w[idx];
    }
    for (int idx = t; idx < 32 * 32; idx += 256) {
        int i = idx >> 5, j = idx & 31;
        l2wT[j * 32 + i] = l2w[idx];
    }
    if (t < 32) {
        l1b_s[t] = l1b[t];
        l2b_s[t] = l2b[t];
        outw_s[t] = outw[t];
    }
    __syncthreads();

    const int w = t >> 5;              // warp 0..7
    const int lane = t & 31;
    const int r = blockIdx.x * 8 + w;
    const int rot = g_stm[r] ? ACC_N : 0;

    // Stage x for this row (stm swap = rotate columns by 128)
    const float* src = g_scratch + (size_t)r * 256;
#pragma unroll
    for (int j = lane; j < 256; j += 32)
        xs[w][j] = src[(j + rot) & 255];
    __syncwarp();

    // Layer 1: lane computes output `lane`
    float o1 = l1b_s[lane];
#pragma unroll 8
    for (int k = 0; k < 256; k++)
        o1 += l1wT[k * 32 + lane] * xs[w][k];
    x1s[w][lane] = screlu(o1);
    __syncwarp();

    // Layer 2
    float o2 = l2b_s[lane];
#pragma unroll
    for (int j = 0; j < 32; j++)
        o2 += l2wT[j * 32 + lane] * x1s[w][j];

    // Output layer: elementwise then warp-reduce
    float v = screlu(o2) * outw_s[lane];
#pragma unroll
    for (int off = 16; off; off >>= 1)
        v += __shfl_xor_sync(0xffffffffu, v, off);
    if (lane == 0) out[r] = v + outb[0];
}

// ---------------------------------------------------------------------------
extern "C" void kernel_launch(void* const* d_in, const int* in_sizes, int n_in,
                              void* d_out, int out_size) {
    const float* white = (const float*)d_in[0];
    const float* black = (const float*)d_in[1];
    const unsigned char* stm = (const unsigned char*)d_in[2];
    const float* ftw  = (const float*)d_in[3];
    const float* ftb  = (const float*)d_in[4];
    const float* l1w  = (const float*)d_in[5];
    const float* l1b  = (const float*)d_in[6];
    const float* l2w  = (const float*)d_in[7];
    const float* l2b  = (const float*)d_in[8];
    const float* outw = (const float*)d_in[9];
    const float* outb = (const float*)d_in[10];
    float* out = (float*)d_out;

    stm_convert_kernel<<<1, 256>>>(stm);
    ft_kernel<<<dim3(B_SZ / 128, 2), 256>>>(white, black, ftw, ftb);
    tail_kernel<<<B_SZ / 8, 256>>>(l1w, l1b, l2w, l2b, outw, outb, out);
}

// round 5
// speedup vs baseline: 2.7423x; 2.7423x over previous
#include <cuda_runtime.h>
#include <cuda_bf16.h>
#include <cstdint>

#define B_SZ 16384
#define F_SZ 9000
#define ACC_N 128

#define BK    16
#define NCH   563            // ceil(9000/16): 562*16=8992, last chunk 8 valid
#define LDK   48             // smem row stride bytes (32B data + 16B pad, 16B-aligned)
#define PLANE (128 * LDK)    // 6144 B
#define STAGE (4 * PLANE)    // Ah, Al, Wh, Wl = 24576 B
#define SMEM_DYN (2 * STAGE) // 49152 B == 48KB exactly, no static smem in this kernel

__device__ float g_scratch[B_SZ * 256];
__device__ int g_mode;

__device__ __forceinline__ float screlu(float x) {
    x = fminf(fmaxf(x, 0.0f), 1.0f);
    return x * x;
}

__device__ __forceinline__ uint32_t smem_u32(const void* p) {
    uint32_t a;
    asm("{ .reg .u64 t; cvta.to.shared.u64 t, %1; cvt.u32.u64 %0, t; }" : "=r"(a) : "l"(p));
    return a;
}

// fp32 pair -> bf16x2 hi + bf16x2 lo (3-term split residual ~2^-18 per product)
__device__ __forceinline__ void split2(float x0, float x1, uint32_t& h, uint32_t& l) {
    asm("cvt.rn.bf16x2.f32 %0, %1, %2;" : "=r"(h) : "f"(x1), "f"(x0));
    float h0 = __uint_as_float(h << 16);
    float h1 = __uint_as_float(h & 0xffff0000u);
    float l0 = x0 - h0;   // exact
    float l1 = x1 - h1;
    asm("cvt.rn.bf16x2.f32 %0, %1, %2;" : "=r"(l) : "f"(l1), "f"(l0));
}

#define LDSM_X4(r, addr)                                                         \
    asm volatile("ldmatrix.sync.aligned.m8n8.x4.shared.b16 {%0,%1,%2,%3}, [%4];" \
                 : "=r"((r)[0]), "=r"((r)[1]), "=r"((r)[2]), "=r"((r)[3])        \
                 : "r"(addr))

#define MMA16816(c, a, bb0, bb1)                                                 \
    asm volatile("mma.sync.aligned.m16n8k16.row.col.f32.bf16.bf16.f32 "          \
                 "{%0,%1,%2,%3}, {%4,%5,%6,%7}, {%8,%9}, {%0,%1,%2,%3};"         \
                 : "+f"((c)[0]), "+f"((c)[1]), "+f"((c)[2]), "+f"((c)[3])        \
                 : "r"((a)[0]), "r"((a)[1]), "r"((a)[2]), "r"((a)[3]),           \
                   "r"(bb0), "r"(bb1))

// ---------------------------------------------------------------------------
// Kernel 0: stm dtype sniff -> g_mode (0=int32, 1=uint8 bool, 2=float32)
// ---------------------------------------------------------------------------
__global__ void stm_detect_kernel(const unsigned char* __restrict__ p) {
    __shared__ int fFloat, fBool;
    if (threadIdx.x == 0) { fFloat = 0; fBool = 0; }
    __syncthreads();
    int lf = 0, lb = 0;
    for (int i = threadIdx.x; i < B_SZ; i += blockDim.x) {
        unsigned char v = p[i];
        if (v == 0x80u || v == 0x3fu) lf = 1;
        else if (v != 0u && (i & 3) != 0) lb = 1;
    }
    if (lf) atomicOr(&fFloat, 1);
    if (lb) atomicOr(&fBool, 1);
    __syncthreads();
    if (threadIdx.x == 0) g_mode = fFloat ? 2 : (fBool ? 1 : 0);
}

// ---------------------------------------------------------------------------
// Kernel 1: feature-transform GEMM on the HMMA tensor pipe (mma.sync bf16,
// 3-term split) + bias + screlu. grid (B/128, 2 colors), 256 thr, occ 2.
// NO static __shared__ here: dynamic smem is exactly 48KB.
// ---------------------------------------------------------------------------
__global__ __launch_bounds__(256, 2)
void ft_mma_kernel(const float* __restrict__ white,
                   const float* __restrict__ black,
                   const float* __restrict__ ftw,
                   const float* __restrict__ ftb) {
    extern __shared__ char smc[];

    const int t = threadIdx.x;
    const int wid = t >> 5;
    const int lane = t & 31;
    const int warp_m = wid >> 2;           // 0..1 -> m offset *64
    const int warp_n = wid & 3;            // 0..3 -> n offset *32
    const int color = blockIdx.y;
    const int row0 = blockIdx.x * 128;
    const float* __restrict__ A = color ? black : white;

    const uint32_t dynBase = smem_u32(smc);

    // loader mapping: 64 rows x 4 float4 per pass, 2 passes
    const int rA = t >> 2;                 // 0..63
    const int c4 = t & 3;                  // float4 idx
    const int kcol = c4 * 4;

    const float* aPtr = A   + (size_t)(row0 + rA) * F_SZ + kcol;
    const float* wPtr = ftw + (size_t)rA * F_SZ + kcol;
    const uint32_t stb = rA * LDK + c4 * 8;   // smem store byte offset (pass 0)

    // ldmatrix lane offsets (within a plane)
    const uint32_t offA0 = (warp_m * 64 + (lane & 15)) * LDK + (lane >> 4) * 16;
    const uint32_t offB0 = (warp_n * 32 + ((lane >> 4) << 3) + (lane & 7)) * LDK
                         + ((lane >> 3) & 1) * 16;

    float acc[4][4][4];
#pragma unroll
    for (int i = 0; i < 4; i++)
#pragma unroll
        for (int j = 0; j < 4; j++)
#pragma unroll
            for (int q = 0; q < 4; q++) acc[i][j][q] = 0.0f;

    float4 aReg[2], wReg[2];

    // ---- preload chunk 0 into stage 0
    {
#pragma unroll
        for (int p = 0; p < 2; p++) {
            aReg[p] = *(const float4*)(aPtr + p * (64 * F_SZ));
            wReg[p] = *(const float4*)(wPtr + p * (64 * F_SZ));
        }
        char* st = smc;
#pragma unroll
        for (int p = 0; p < 2; p++) {
            uint32_t h0, l0, h1, l1;
            const uint32_t o = stb + p * (64 * LDK);
            split2(aReg[p].x, aReg[p].y, h0, l0);
            split2(aReg[p].z, aReg[p].w, h1, l1);
            *(uint2*)(st + 0 * PLANE + o) = make_uint2(h0, h1);
            *(uint2*)(st + 1 * PLANE + o) = make_uint2(l0, l1);
            split2(wReg[p].x, wReg[p].y, h0, l0);
            split2(wReg[p].z, wReg[p].w, h1, l1);
            *(uint2*)(st + 2 * PLANE + o) = make_uint2(h0, h1);
            *(uint2*)(st + 3 * PLANE + o) = make_uint2(l0, l1);
        }
    }
    __syncthreads();

    for (int c = 0; c < NCH; ++c) {
        const int cur = c & 1;
        const bool more = (c + 1) < NCH;

        // ---- issue prefetch of chunk c+1 (gmem -> regs)
        if (more) {
            const int k0 = (c + 1) * BK;
            const bool ok = (k0 + kcol) < F_SZ;
#pragma unroll
            for (int p = 0; p < 2; p++) {
                aReg[p] = ok ? *(const float4*)(aPtr + k0 + p * (64 * F_SZ))
                             : make_float4(0, 0, 0, 0);
                wReg[p] = ok ? *(const float4*)(wPtr + k0 + p * (64 * F_SZ))
                             : make_float4(0, 0, 0, 0);
            }
        }

        // ---- MMA on stage cur
        {
            const uint32_t sb = dynBase + cur * STAGE;
            const uint32_t ah_b = sb + 0 * PLANE;
            const uint32_t al_b = sb + 1 * PLANE;
            const uint32_t wh_b = sb + 2 * PLANE;
            const uint32_t wl_b = sb + 3 * PLANE;

            uint32_t af[4][4], bh[2][4], bl[2][4];
#pragma unroll
            for (int mi = 0; mi < 4; mi++) LDSM_X4(af[mi], ah_b + offA0 + mi * (16 * LDK));
#pragma unroll
            for (int q = 0; q < 2; q++)  LDSM_X4(bh[q], wh_b + offB0 + q * (16 * LDK));
            // Ah * Wh
#pragma unroll
            for (int mi = 0; mi < 4; mi++)
#pragma unroll
                for (int ni = 0; ni < 4; ni++) {
                    const int q = ni >> 1, r = (ni & 1) * 2;
                    MMA16816(acc[mi][ni], af[mi], bh[q][r], bh[q][r + 1]);
                }
#pragma unroll
            for (int q = 0; q < 2; q++)  LDSM_X4(bl[q], wl_b + offB0 + q * (16 * LDK));
            // Ah * Wl
#pragma unroll
            for (int mi = 0; mi < 4; mi++)
#pragma unroll
                for (int ni = 0; ni < 4; ni++) {
                    const int q = ni >> 1, r = (ni & 1) * 2;
                    MMA16816(acc[mi][ni], af[mi], bl[q][r], bl[q][r + 1]);
                }
#pragma unroll
            for (int mi = 0; mi < 4; mi++) LDSM_X4(af[mi], al_b + offA0 + mi * (16 * LDK));
            // Al * Wh
#pragma unroll
            for (int mi = 0; mi < 4; mi++)
#pragma unroll
                for (int ni = 0; ni < 4; ni++) {
                    const int q = ni >> 1, r = (ni & 1) * 2;
                    MMA16816(acc[mi][ni], af[mi], bh[q][r], bh[q][r + 1]);
                }
        }

        // ---- convert + store chunk c+1 into the other stage
        if (more) {
            char* st = smc + ((c + 1) & 1) * STAGE;
#pragma unroll
            for (int p = 0; p < 2; p++) {
                uint32_t h0, l0, h1, l1;
                const uint32_t o = stb + p * (64 * LDK);
                split2(aReg[p].x, aReg[p].y, h0, l0);
                split2(aReg[p].z, aReg[p].w, h1, l1);
                *(uint2*)(st + 0 * PLANE + o) = make_uint2(h0, h1);
                *(uint2*)(st + 1 * PLANE + o) = make_uint2(l0, l1);
                split2(wReg[p].x, wReg[p].y, h0, l0);
                split2(wReg[p].z, wReg[p].w, h1, l1);
                *(uint2*)(st + 2 * PLANE + o) = make_uint2(h0, h1);
                *(uint2*)(st + 3 * PLANE + o) = make_uint2(l0, l1);
            }
        }
        __syncthreads();
    }

    // ---- epilogue: bias (from gmem, L1-cached) + screlu -> g_scratch
    float2 bias[4];
#pragma unroll
    for (int ni = 0; ni < 4; ni++) {
        const int n = warp_n * 32 + ni * 8 + (lane & 3) * 2;
        bias[ni] = *(const float2*)(ftb + n);
    }
#pragma unroll
    for (int mi = 0; mi < 4; mi++) {
#pragma unroll
        for (int half = 0; half < 2; half++) {
            const int m = warp_m * 64 + mi * 16 + (lane >> 2) + half * 8;
            float* dstRow = g_scratch + (size_t)(row0 + m) * 256 + color * ACC_N;
#pragma unroll
            for (int ni = 0; ni < 4; ni++) {
                const int n = warp_n * 32 + ni * 8 + (lane & 3) * 2;
                float2 o;
                o.x = screlu(acc[mi][ni][half * 2 + 0] + bias[ni].x);
                o.y = screlu(acc[mi][ni][half * 2 + 1] + bias[ni].y);
                *(float2*)(dstRow + n) = o;
            }
        }
    }
}

// ---------------------------------------------------------------------------
// Kernel 2: tail MLP, one warp per batch row; stm decoded inline via g_mode.
// ---------------------------------------------------------------------------
__global__ __launch_bounds__(256)
void tail_kernel(const unsigned char* __restrict__ stm,
                 const float* __restrict__ l1w, const float* __restrict__ l1b,
                 const float* __restrict__ l2w, const float* __restrict__ l2b,
                 const float* __restrict__ outw, const float* __restrict__ outb,
                 float* __restrict__ out) {
    __shared__ float l1wT[256 * 32];
    __shared__ float l1b_s[32];
    __shared__ float l2wT[32 * 32];
    __shared__ float l2b_s[32];
    __shared__ float outw_s[32];
    __shared__ float xs[8][256];
    __shared__ float x1s[8][32];

    const int t = threadIdx.x;
    for (int idx = t; idx < 32 * 256; idx += 256) {
        int i = idx >> 8, k = idx & 255;
        l1wT[k * 32 + i] = l1w[idx];
    }
    for (int idx = t; idx < 32 * 32; idx += 256) {
        int i = idx >> 5, j = idx & 31;
        l2wT[j * 32 + i] = l2w[idx];
    }
    if (t < 32) {
        l1b_s[t] = l1b[t];
        l2b_s[t] = l2b[t];
        outw_s[t] = outw[t];
    }
    __syncthreads();

    const int w = t >> 5;
    const int lane = t & 31;
    const int r = blockIdx.x * 8 + w;

    const int mode = g_mode;
    bool s;
    if (mode == 2)      s = (((const float*)(const void*)stm)[r] != 0.0f);
    else if (mode == 1) s = (stm[r] != 0u);
    else                s = (((const int*)(const void*)stm)[r] != 0);
    const int rot = s ? ACC_N : 0;

    const float* src = g_scratch + (size_t)r * 256;
#pragma unroll
    for (int j = lane; j < 256; j += 32)
        xs[w][j] = src[(j + rot) & 255];
    __syncwarp();

    float o1 = l1b_s[lane];
#pragma unroll 8
    for (int k = 0; k < 256; k++)
        o1 += l1wT[k * 32 + lane] * xs[w][k];
    x1s[w][lane] = screlu(o1);
    __syncwarp();

    float o2 = l2b_s[lane];
#pragma unroll
    for (int j = 0; j < 32; j++)
        o2 += l2wT[j * 32 + lane] * x1s[w][j];

    float v = screlu(o2) * outw_s[lane];
#pragma unroll
    for (int off = 16; off; off >>= 1)
        v += __shfl_xor_sync(0xffffffffu, v, off);
    if (lane == 0) out[r] = v + outb[0];
}

// ---------------------------------------------------------------------------
extern "C" void kernel_launch(void* const* d_in, const int* in_sizes, int n_in,
                              void* d_out, int out_size) {
    const float* white = (const float*)d_in[0];
    const float* black = (const float*)d_in[1];
    const unsigned char* stm = (const unsigned char*)d_in[2];
    const float* ftw  = (const float*)d_in[3];
    const float* ftb  = (const float*)d_in[4];
    const float* l1w  = (const float*)d_in[5];
    const float* l1b  = (const float*)d_in[6];
    const float* l2w  = (const float*)d_in[7];
    const float* l2b  = (const float*)d_in[8];
    const float* outw = (const float*)d_in[9];
    const float* outb = (const float*)d_in[10];
    float* out = (float*)d_out;

    stm_detect_kernel<<<1, 1024>>>(stm);
    ft_mma_kernel<<<dim3(B_SZ / 128, 2), 256, SMEM_DYN>>>(white, black, ftw, ftb);
    tail_kernel<<<B_SZ / 8, 256>>>(stm, l1w, l1b, l2w, l2b, outw, outb, out);
}